// round 8
// baseline (speedup 1.0000x reference)
#include <cuda_runtime.h>
#include <cuda_fp16.h>
#include <mma.h>
#include <cstdint>

using namespace nvcuda;

// ---------------- problem constants ----------------
#define K_DIM 4096
#define N_DIM 11008
#define M_DIM 8192

// ---------------- tiling ----------------
#define BM 128
#define BN 128
#define BK 64
#define KT (K_DIM / BK)      // 64
#define NTHREADS 128         // 4 warps, 2x2 grid of 64x64 warp tiles
#define LDT 72               // padded smem stride in halves (144B rows)

// smem byte offsets (dynamic)
#define A_BYTES (BM * LDT * 2)      // 18432
#define B_BYTES (BN * LDT * 2)      // 18432
#define OFF_A0 0
#define OFF_A1 (A_BYTES)
#define OFF_B0 (2 * A_BYTES)
#define OFF_B1 (2 * A_BYTES + B_BYTES)
#define SMEM_TOTAL (2 * A_BYTES + 2 * B_BYTES)   // 73728 -> 2 CTAs/SM

// fp16 copy of x with k-permutation [0,4,1,5,2,6,3,7] within each 8-group
// (fp32 inputs are exact fp16 values -> lossless)
__device__ __half g_xh[(size_t)M_DIM * K_DIM];

__device__ __forceinline__ uint32_t smem_u32(const void* p) {
    uint32_t a;
    asm("{ .reg .u64 t; cvta.to.shared.u64 t, %1; cvt.u32.u64 %0, t; }" : "=r"(a) : "l"(p));
    return a;
}
__device__ __forceinline__ void cp_async16(uint32_t dst, const void* src) {
    asm volatile("cp.async.cg.shared.global [%0], [%1], 16;" :: "r"(dst), "l"(src) : "memory");
}
__device__ __forceinline__ void cp_commit() {
    asm volatile("cp.async.commit_group;" ::: "memory");
}
__device__ __forceinline__ void cp_wait0() {
    asm volatile("cp.async.wait_group 0;" ::: "memory");
}

// ---------------- pre-pass: x fp32 -> fp16, k-pair-permuted ----------------
// output order per 8-group: (f0,f4),(f1,f5),(f2,f6),(f3,f7)
__global__ __launch_bounds__(256) void convert_x_kernel(const float* __restrict__ x) {
    size_t i = (size_t)blockIdx.x * 256 + threadIdx.x;   // one uint4 (8 halves) per thread
    const float4* p = reinterpret_cast<const float4*>(x) + 2 * i;
    float4 a = p[0], b = p[1];   // a = k0..k3, b = k4..k7
    __half2 h[4];
    h[0] = __floats2half2_rn(a.x, b.x);   // (k0, k4)
    h[1] = __floats2half2_rn(a.y, b.y);   // (k1, k5)
    h[2] = __floats2half2_rn(a.z, b.z);   // (k2, k6)
    h[3] = __floats2half2_rn(a.w, b.w);   // (k3, k7)
    reinterpret_cast<uint4*>(g_xh)[i] = *reinterpret_cast<uint4*>(h);
}

// ---------------- main fused dequant-GEMM ----------------
__global__ __launch_bounds__(NTHREADS, 2)
void gptq_gemm_kernel(const int*   __restrict__ qw,
                      const float* __restrict__ scales,
                      const float* __restrict__ bias,
                      float*       __restrict__ out)
{
    extern __shared__ __align__(128) char smem[];
    const uint32_t sb = smem_u32(smem);

    const int tid     = threadIdx.x;
    const int warp_id = tid >> 5;
    const int lane    = tid & 31;
    const int m0 = blockIdx.y * BM;
    const int n0 = blockIdx.x * BN;

    // warp grid: 2 along M x 2 along N, each warp owns 64x64
    const int wm = warp_id & 1;
    const int wn = warp_id >> 1;

    wmma::fragment<wmma::accumulator, 16, 16, 16, float> cf[4][4];
    #pragma unroll
    for (int i = 0; i < 4; i++)
        #pragma unroll
        for (int j = 0; j < 4; j++)
            wmma::fill_fragment(cf[i][j], 0.0f);

    // ---- depth-2 B register pipeline (one n-column per thread) ----
    int     wreg[2][8];
    __half2 s2[2];
    const int n = tid;  // 0..127

    auto ldgB = [&](int kt, int slot) {
        const int k0 = kt * BK;
        float sf = scales[(size_t)(k0 >> 7) * N_DIM + n0 + n];
        s2[slot] = __half2half2(__float2half(sf));
        const int* qp = qw + (size_t)(k0 >> 3) * N_DIM + n0 + n;
        #pragma unroll
        for (int r = 0; r < 8; r++)
            wreg[slot][r] = qp[(size_t)r * N_DIM];
    };

    const __half2 c1032 = __floats2half2_rn(1032.0f, 1032.0f);

    // dequant one packed word -> 16B smem chunk, permuted pair order
    auto deq_word = [&](int slot, int r, uint32_t b_off) {
        unsigned q = (unsigned)wreg[slot][r];
        __half2 s = s2[slot];
        unsigned y0 = (q          & 0x000f000fu) | 0x64006400u;  // (k0,k4)+1024
        unsigned y1 = ((q >> 4)   & 0x000f000fu) | 0x64006400u;  // (k1,k5)+1024
        unsigned y2 = ((q >> 8)   & 0x000f000fu) | 0x64006400u;  // (k2,k6)+1024
        unsigned y3 = ((q >> 12)  & 0x000f000fu) | 0x64006400u;  // (k3,k7)+1024
        __half2 v[4];
        v[0] = __hmul2(__hsub2(*reinterpret_cast<__half2*>(&y0), c1032), s);
        v[1] = __hmul2(__hsub2(*reinterpret_cast<__half2*>(&y1), c1032), s);
        v[2] = __hmul2(__hsub2(*reinterpret_cast<__half2*>(&y2), c1032), s);
        v[3] = __hmul2(__hsub2(*reinterpret_cast<__half2*>(&y3), c1032), s);
        *reinterpret_cast<uint4*>(smem + b_off + n * (LDT * 2) + r * 16) =
            *reinterpret_cast<uint4*>(v);
    };

    auto cpA = [&](int kt, uint32_t a_off) {
        const int k0 = kt * BK;
        #pragma unroll
        for (int r = 0; r < 8; r++) {
            int idx = tid + NTHREADS * r;          // 0..1023
            int row = idx >> 3, c = idx & 7;
            cp_async16(sb + a_off + (uint32_t)(row * (LDT * 2) + c * 16),
                       g_xh + (size_t)(m0 + row) * K_DIM + k0 + c * 8);
        }
        cp_commit();
    };

    // ---- prologue ----
    cpA(0, OFF_A0);
    ldgB(0, 0);
    ldgB(1, 1);
    #pragma unroll
    for (int r = 0; r < 8; r++) deq_word(0, r, OFF_B0);   // B(0) -> B0

    for (int kt = 0; kt < KT; kt++) {
        const int buf = kt & 1;
        const uint32_t a_off  = buf ? OFF_A1 : OFF_A0;
        const uint32_t b_off  = buf ? OFF_B1 : OFF_B0;
        const uint32_t a_next = buf ? OFF_A0 : OFF_A1;
        const uint32_t b_next = buf ? OFF_B0 : OFF_B1;
        const bool has_next = (kt + 1 < KT);
        const int  nslot    = (kt + 1) & 1;

        cp_wait0();          // A(kt) resident
        __syncthreads();     // (A,B)(kt) visible; all warps done with kt-1 buffers

        if (has_next)      cpA(kt + 1, a_next);
        if (kt + 2 < KT)   ldgB(kt + 2, kt & 1);   // overwrite consumed slot

        // ---- tensor compute on smem[buf], dequant(kt+1) interleaved ----
        const __half* As = reinterpret_cast<const __half*>(smem + a_off);
        const __half* Bs = reinterpret_cast<const __half*>(smem + b_off);
        #pragma unroll
        for (int ks = 0; ks < BK / 16; ks++) {
            wmma::fragment<wmma::matrix_a, 16, 16, 16, __half, wmma::row_major> af[4];
            wmma::fragment<wmma::matrix_b, 16, 16, 16, __half, wmma::col_major> bf[4];
            #pragma unroll
            for (int i = 0; i < 4; i++)
                wmma::load_matrix_sync(af[i], As + (wm * 64 + i * 16) * LDT + ks * 16, LDT);
            #pragma unroll
            for (int j = 0; j < 4; j++)
                wmma::load_matrix_sync(bf[j], Bs + (wn * 64 + j * 16) * LDT + ks * 16, LDT);
            #pragma unroll
            for (int i = 0; i < 4; i++)
                #pragma unroll
                for (int j = 0; j < 4; j++)
                    wmma::mma_sync(cf[i][j], af[i], bf[j], cf[i][j]);
            if (has_next) {           // 2 words per ks step, hidden in MMA slots
                deq_word(nslot, ks * 2 + 0, b_next);
                deq_word(nslot, ks * 2 + 1, b_next);
            }
        }
    }

    // ---- epilogue: strip-staged, coalesced, fused bias ----
    __syncthreads();   // everyone done with smem tiles; reuse as staging
    float* stage = reinterpret_cast<float*>(smem) + warp_id * (17 * 64);

    const int row0 = m0 + wm * 64;
    const int col0 = n0 + wn * 64;

    #pragma unroll
    for (int i = 0; i < 4; i++) {
        #pragma unroll
        for (int j = 0; j < 4; j++)
            wmma::store_matrix_sync(stage + j * 16, cf[i][j], 68, wmma::mem_row_major);
        __syncwarp();
        #pragma unroll
        for (int q = 0; q < 8; q++) {
            int idx = q * 32 + lane;       // 0..255 float4s
            int r  = idx >> 4;
            int c4 = idx & 15;
            float4 v = *reinterpret_cast<const float4*>(stage + r * 68 + c4 * 4);
            const float4 bb = *reinterpret_cast<const float4*>(bias + col0 + c4 * 4);
            v.x += bb.x; v.y += bb.y; v.z += bb.z; v.w += bb.w;
            *reinterpret_cast<float4*>(
                out + (size_t)(row0 + i * 16 + r) * N_DIM + col0 + c4 * 4) = v;
        }
        __syncwarp();
    }
}

extern "C" void kernel_launch(void* const* d_in, const int* in_sizes, int n_in,
                              void* d_out, int out_size)
{
    const float* x      = (const float*)d_in[0];
    const int*   qw     = (const int*)d_in[1];
    const float* scales = (const float*)d_in[2];
    const float* bias   = (const float*)d_in[3];
    float* out = (float*)d_out;

    cudaFuncSetAttribute(gptq_gemm_kernel,
                         cudaFuncAttributeMaxDynamicSharedMemorySize, SMEM_TOTAL);

    // pre-pass: fp32 -> fp16 permuted (8 halves per thread)
    convert_x_kernel<<<(M_DIM * K_DIM) / 8 / 256, 256>>>(x);

    dim3 grid(N_DIM / BN, M_DIM / BM);   // (86, 64)
    gptq_gemm_kernel<<<grid, NTHREADS, SMEM_TOTAL>>>(qw, scales, bias, out);
}

// round 9
// speedup vs baseline: 1.3533x; 1.3533x over previous
#include <cuda_runtime.h>
#include <cuda_fp16.h>
#include <mma.h>
#include <cstdint>

using namespace nvcuda;

// ---------------- problem constants ----------------
#define K_DIM 4096
#define N_DIM 11008
#define M_DIM 8192

// ---------------- tiling ----------------
#define BM 128
#define BN 128
#define BK 64
#define KT (K_DIM / BK)      // 64
#define NTHREADS 128         // 4 warps, 2x2 grid of 64x64 warp tiles
#define LDT 72               // padded smem stride in halves (144B rows)

// smem byte offsets (dynamic): 3 A buffers, 2 B buffers
#define A_BYTES (BM * LDT * 2)      // 18432
#define B_BYTES (BN * LDT * 2)      // 18432
#define OFF_A0 0
#define OFF_A1 (A_BYTES)
#define OFF_A2 (2 * A_BYTES)
#define OFF_B0 (3 * A_BYTES)
#define OFF_B1 (3 * A_BYTES + B_BYTES)
#define SMEM_TOTAL (3 * A_BYTES + 2 * B_BYTES)   // 92160 -> 2 CTAs/SM

// fp16 copy of x with k-permutation [0,4,1,5,2,6,3,7] within each 8-group
// (fp32 inputs are exact fp16 values -> lossless)
__device__ __half g_xh[(size_t)M_DIM * K_DIM];

__device__ __forceinline__ uint32_t smem_u32(const void* p) {
    uint32_t a;
    asm("{ .reg .u64 t; cvta.to.shared.u64 t, %1; cvt.u32.u64 %0, t; }" : "=r"(a) : "l"(p));
    return a;
}
__device__ __forceinline__ void cp_async16(uint32_t dst, const void* src) {
    asm volatile("cp.async.cg.shared.global [%0], [%1], 16;" :: "r"(dst), "l"(src) : "memory");
}
__device__ __forceinline__ void cp_commit() {
    asm volatile("cp.async.commit_group;" ::: "memory");
}
__device__ __forceinline__ void cp_wait0() {
    asm volatile("cp.async.wait_group 0;" ::: "memory");
}
__device__ __forceinline__ void cp_wait1() {
    asm volatile("cp.async.wait_group 1;" ::: "memory");
}

// ---------------- pre-pass: x fp32 -> fp16, k-pair-permuted ----------------
// output order per 8-group: (f0,f4),(f1,f5),(f2,f6),(f3,f7)
__global__ __launch_bounds__(256) void convert_x_kernel(const float* __restrict__ x) {
    size_t i = (size_t)blockIdx.x * 256 + threadIdx.x;   // one uint4 (8 halves) per thread
    const float4* p = reinterpret_cast<const float4*>(x) + 2 * i;
    float4 a = p[0], b = p[1];   // a = k0..k3, b = k4..k7
    __half2 h[4];
    h[0] = __floats2half2_rn(a.x, b.x);   // (k0, k4)
    h[1] = __floats2half2_rn(a.y, b.y);   // (k1, k5)
    h[2] = __floats2half2_rn(a.z, b.z);   // (k2, k6)
    h[3] = __floats2half2_rn(a.w, b.w);   // (k3, k7)
    reinterpret_cast<uint4*>(g_xh)[i] = *reinterpret_cast<uint4*>(h);
}

// ---------------- main fused dequant-GEMM ----------------
__global__ __launch_bounds__(NTHREADS, 2)
void gptq_gemm_kernel(const int*   __restrict__ qw,
                      const float* __restrict__ scales,
                      const float* __restrict__ bias,
                      float*       __restrict__ out)
{
    extern __shared__ __align__(128) char smem[];
    const uint32_t sb = smem_u32(smem);

    const int tid     = threadIdx.x;
    const int warp_id = tid >> 5;
    const int lane    = tid & 31;
    const int m0 = blockIdx.y * BM;
    const int n0 = blockIdx.x * BN;

    // warp grid: 2 along M x 2 along N, each warp owns 64x64
    const int wm = warp_id & 1;
    const int wn = warp_id >> 1;

    wmma::fragment<wmma::accumulator, 16, 16, 16, float> cf[4][4];
    #pragma unroll
    for (int i = 0; i < 4; i++)
        #pragma unroll
        for (int j = 0; j < 4; j++)
            wmma::fill_fragment(cf[i][j], 0.0f);

    // ---- B register prefetch state (one n-column per thread) ----
    int     wreg[8];
    __half2 s2;
    const int n = tid;  // 0..127

    auto ldgB = [&](int kt) {
        const int k0 = kt * BK;
        float sf = scales[(size_t)(k0 >> 7) * N_DIM + n0 + n];
        s2 = __half2half2(__float2half(sf));
        const int* qp = qw + (size_t)(k0 >> 3) * N_DIM + n0 + n;
        #pragma unroll
        for (int r = 0; r < 8; r++)
            wreg[r] = qp[(size_t)r * N_DIM];
    };

    auto cpA = [&](int kt, uint32_t a_off) {
        const int k0 = kt * BK;
        #pragma unroll
        for (int r = 0; r < 8; r++) {
            int idx = tid + NTHREADS * r;          // 0..1023
            int row = idx >> 3, c = idx & 7;
            cp_async16(sb + a_off + (uint32_t)(row * (LDT * 2) + c * 16),
                       g_xh + (size_t)(m0 + row) * K_DIM + k0 + c * 8);
        }
        cp_commit();
    };

    const __half2 c1032 = __floats2half2_rn(1032.0f, 1032.0f);
    const uint32_t a_offs[3] = {OFF_A0, OFF_A1, OFF_A2};

    // ---- prologue: A(0), A(1) in flight; B(0) words in regs ----
    cpA(0, OFF_A0);
    cpA(1, OFF_A1);
    ldgB(0);

    int a_idx = 0;  // kt % 3

    for (int kt = 0; kt < KT; kt++) {
        const uint32_t a_off = a_offs[a_idx];
        const uint32_t b_off = (kt & 1) ? OFF_B1 : OFF_B0;

        // ---- dequant B(kt) regs -> smem (bulk phase, nibble-pair form) ----
        #pragma unroll
        for (int r = 0; r < 8; r++) {
            unsigned q = (unsigned)wreg[r];
            unsigned y0 = (q         & 0x000f000fu) | 0x64006400u;  // (k0,k4)+1024
            unsigned y1 = ((q >> 4)  & 0x000f000fu) | 0x64006400u;  // (k1,k5)+1024
            unsigned y2 = ((q >> 8)  & 0x000f000fu) | 0x64006400u;  // (k2,k6)+1024
            unsigned y3 = ((q >> 12) & 0x000f000fu) | 0x64006400u;  // (k3,k7)+1024
            __half2 v[4];
            v[0] = __hmul2(__hsub2(*reinterpret_cast<__half2*>(&y0), c1032), s2);
            v[1] = __hmul2(__hsub2(*reinterpret_cast<__half2*>(&y1), c1032), s2);
            v[2] = __hmul2(__hsub2(*reinterpret_cast<__half2*>(&y2), c1032), s2);
            v[3] = __hmul2(__hsub2(*reinterpret_cast<__half2*>(&y3), c1032), s2);
            *reinterpret_cast<uint4*>(smem + b_off + n * (LDT * 2) + r * 16) =
                *reinterpret_cast<uint4*>(v);
        }

        // A(kt) resident: allow 1 outstanding group (A(kt+1)) when it exists
        if (kt + 2 < KT) cp_wait1(); else cp_wait0();
        __syncthreads();     // (A,B)(kt) visible; all warps done with old buffers

        // ---- prefetch: A two ahead, B one ahead (overlap with MMA below) ----
        if (kt + 2 < KT) {
            int nxt = a_idx + 2; if (nxt >= 3) nxt -= 3;
            cpA(kt + 2, a_offs[nxt]);
        }
        if (kt + 1 < KT) ldgB(kt + 1);

        // ---- pure tensor phase on smem tiles ----
        const __half* As = reinterpret_cast<const __half*>(smem + a_off);
        const __half* Bs = reinterpret_cast<const __half*>(smem + b_off);
        #pragma unroll
        for (int ks = 0; ks < BK / 16; ks++) {
            wmma::fragment<wmma::matrix_a, 16, 16, 16, __half, wmma::row_major> af[4];
            wmma::fragment<wmma::matrix_b, 16, 16, 16, __half, wmma::col_major> bf[4];
            #pragma unroll
            for (int i = 0; i < 4; i++)
                wmma::load_matrix_sync(af[i], As + (wm * 64 + i * 16) * LDT + ks * 16, LDT);
            #pragma unroll
            for (int j = 0; j < 4; j++)
                wmma::load_matrix_sync(bf[j], Bs + (wn * 64 + j * 16) * LDT + ks * 16, LDT);
            #pragma unroll
            for (int i = 0; i < 4; i++)
                #pragma unroll
                for (int j = 0; j < 4; j++)
                    wmma::mma_sync(cf[i][j], af[i], bf[j], cf[i][j]);
        }

        if (++a_idx == 3) a_idx = 0;
    }

    // ---- epilogue: strip-staged, coalesced, fused bias ----
    __syncthreads();   // everyone done with smem tiles; reuse as staging
    float* stage = reinterpret_cast<float*>(smem) + warp_id * (17 * 64);

    const int row0 = m0 + wm * 64;
    const int col0 = n0 + wn * 64;

    #pragma unroll
    for (int i = 0; i < 4; i++) {
        #pragma unroll
        for (int j = 0; j < 4; j++)
            wmma::store_matrix_sync(stage + j * 16, cf[i][j], 68, wmma::mem_row_major);
        __syncwarp();
        #pragma unroll
        for (int q = 0; q < 8; q++) {
            int idx = q * 32 + lane;       // 0..255 float4s
            int r  = idx >> 4;
            int c4 = idx & 15;
            float4 v = *reinterpret_cast<const float4*>(stage + r * 68 + c4 * 4);
            const float4 bb = *reinterpret_cast<const float4*>(bias + col0 + c4 * 4);
            v.x += bb.x; v.y += bb.y; v.z += bb.z; v.w += bb.w;
            *reinterpret_cast<float4*>(
                out + (size_t)(row0 + i * 16 + r) * N_DIM + col0 + c4 * 4) = v;
        }
        __syncwarp();
    }
}

extern "C" void kernel_launch(void* const* d_in, const int* in_sizes, int n_in,
                              void* d_out, int out_size)
{
    const float* x      = (const float*)d_in[0];
    const int*   qw     = (const int*)d_in[1];
    const float* scales = (const float*)d_in[2];
    const float* bias   = (const float*)d_in[3];
    float* out = (float*)d_out;

    cudaFuncSetAttribute(gptq_gemm_kernel,
                         cudaFuncAttributeMaxDynamicSharedMemorySize, SMEM_TOTAL);

    // pre-pass: fp32 -> fp16 permuted (8 halves per thread)
    convert_x_kernel<<<(M_DIM * K_DIM) / 8 / 256, 256>>>(x);

    dim3 grid(N_DIM / BN, M_DIM / BM);   // (86, 64)
    gptq_gemm_kernel<<<grid, NTHREADS, SMEM_TOTAL>>>(qw, scales, bias, out);
}